// round 1
// baseline (speedup 1.0000x reference)
#include <cuda_runtime.h>
#include <cuda_bf16.h>

#define N_NODES  50000
#define N_EDGES  800000
#define N_GRAPHS 1024
#define N_PAIRS  16384
#define N_CL     16
#define IN_CH    64
#define EMB      128
#define HID      256

// ---------------- scratch (device globals; no allocations) ----------------
__device__ float g_bufHW[N_NODES * EMB];    // hw (h @ W), 25.6 MB
__device__ float g_bufAGG[N_NODES * EMB];   // aggregation accumulator, 25.6 MB
__device__ int   g_deg[N_NODES];
__device__ float g_dinv[N_NODES];
__device__ float g_gsum[N_GRAPHS * EMB];    // graph sums -> graph embeddings (in place)
__device__ float g_cnt[N_GRAPHS];
__device__ int   g_clcnt[N_CL];
__device__ int   g_offs[N_CL + 1];
__device__ int   g_cursor[N_CL];
__device__ int   g_sorted[N_PAIRS];

// ---------------- init ----------------
__global__ void init_kernel() {
    int i = blockIdx.x * blockDim.x + threadIdx.x;
    if (i < N_GRAPHS * EMB) g_gsum[i] = 0.f;
    if (i < N_NODES)  g_deg[i] = 1;            // self-loop
    if (i < N_GRAPHS) g_cnt[i] = 0.f;
    if (i < N_CL)     g_clcnt[i] = 0;
}

// ---------------- degree / dinv ----------------
__global__ void degree_kernel(const int* __restrict__ ei) {
    int e = blockIdx.x * blockDim.x + threadIdx.x;
    if (e < N_EDGES) atomicAdd(&g_deg[ei[N_EDGES + e]], 1);  // target = col
}

__global__ void dinv_kernel() {
    int n = blockIdx.x * blockDim.x + threadIdx.x;
    if (n < N_NODES) g_dinv[n] = rsqrtf((float)g_deg[n]);
}

// ---------------- node-feature GEMM: Y[n,128] = (relu?)X[n,K] @ W[K,128] ----------------
// 64 nodes per block, 256 threads, thread owns 4 nodes x 8 cols.
__global__ void gemm_node(const float* __restrict__ X, const float* __restrict__ W,
                          float* __restrict__ Y, int n, int K, int doRelu) {
    __shared__ float Xs[64 * 64];
    __shared__ float Ws[64 * 128];
    int tid = threadIdx.x;
    int cg = tid & 15;       // col group: cols cg*8 .. cg*8+7
    int ng = tid >> 4;       // node group: nodes ng*4 .. ng*4+3
    int n0 = blockIdx.x * 64;

    float acc[4][8];
#pragma unroll
    for (int j = 0; j < 4; j++)
#pragma unroll
        for (int q = 0; q < 8; q++) acc[j][q] = 0.f;

    for (int kt = 0; kt < K; kt += 64) {
#pragma unroll
        for (int i = tid; i < 64 * 128; i += 256) Ws[i] = W[kt * 128 + i];
#pragma unroll
        for (int i = tid; i < 64 * 64; i += 256) {
            int nl = i >> 6, kk = i & 63;
            int node = n0 + nl;
            float v = (node < n) ? X[node * K + kt + kk] : 0.f;
            if (doRelu) v = fmaxf(v, 0.f);
            Xs[nl * 64 + kk] = v;
        }
        __syncthreads();
#pragma unroll 8
        for (int kk = 0; kk < 64; kk++) {
            float4 wa = *(const float4*)&Ws[kk * 128 + cg * 8];
            float4 wb = *(const float4*)&Ws[kk * 128 + cg * 8 + 4];
#pragma unroll
            for (int j = 0; j < 4; j++) {
                float xv = Xs[(ng * 4 + j) * 64 + kk];
                acc[j][0] = fmaf(xv, wa.x, acc[j][0]);
                acc[j][1] = fmaf(xv, wa.y, acc[j][1]);
                acc[j][2] = fmaf(xv, wa.z, acc[j][2]);
                acc[j][3] = fmaf(xv, wa.w, acc[j][3]);
                acc[j][4] = fmaf(xv, wb.x, acc[j][4]);
                acc[j][5] = fmaf(xv, wb.y, acc[j][5]);
                acc[j][6] = fmaf(xv, wb.z, acc[j][6]);
                acc[j][7] = fmaf(xv, wb.w, acc[j][7]);
            }
        }
        __syncthreads();
    }
#pragma unroll
    for (int j = 0; j < 4; j++) {
        int node = n0 + ng * 4 + j;
        if (node < n) {
            float4 a = make_float4(acc[j][0], acc[j][1], acc[j][2], acc[j][3]);
            float4 b = make_float4(acc[j][4], acc[j][5], acc[j][6], acc[j][7]);
            *(float4*)&Y[node * 128 + cg * 8]     = a;
            *(float4*)&Y[node * 128 + cg * 8 + 4] = b;
        }
    }
}

// ---------------- agg init: agg[n] = dinv[n]^2 * hw[n] + bias (self-loop + bias) ----------------
__global__ void agg_init(const float4* __restrict__ hw, const float4* __restrict__ bias,
                         float4* __restrict__ agg) {
    int idx = blockIdx.x * blockDim.x + threadIdx.x;
    if (idx >= N_NODES * 32) return;
    int n = idx >> 5, k4 = idx & 31;
    float d = g_dinv[n];
    float s = d * d;
    float4 h = hw[idx];
    float4 b = bias[k4];
    float4 o;
    o.x = fmaf(s, h.x, b.x); o.y = fmaf(s, h.y, b.y);
    o.z = fmaf(s, h.z, b.z); o.w = fmaf(s, h.w, b.w);
    agg[idx] = o;
}

// ---------------- edge aggregation: agg[col] += dinv[row]*dinv[col] * hw[row] ----------------
// one warp per edge, one float4 per lane, vector reduction atomic
__global__ void agg_edges(const float4* __restrict__ hw, const int* __restrict__ ei,
                          float* __restrict__ agg) {
    unsigned gtid = blockIdx.x * blockDim.x + threadIdx.x;
    int e = gtid >> 5;
    if (e >= N_EDGES) return;
    int lane = threadIdx.x & 31;
    int r = ei[e];
    int c = ei[N_EDGES + e];
    float nrm = g_dinv[r] * g_dinv[c];
    float4 v = hw[r * 32 + lane];
    v.x *= nrm; v.y *= nrm; v.z *= nrm; v.w *= nrm;
    float* p = agg + c * 128 + lane * 4;
    asm volatile("red.global.add.v4.f32 [%0], {%1,%2,%3,%4};"
                 :: "l"(p), "f"(v.x), "f"(v.y), "f"(v.z), "f"(v.w) : "memory");
}

// ---------------- pooling: gsum[batch[n]] += relu(agg2[n]); cnt[batch[n]] += 1 ----------------
__global__ void pool_kernel(const float4* __restrict__ h2pre, const int* __restrict__ batch) {
    unsigned gtid = blockIdx.x * blockDim.x + threadIdx.x;
    int n = gtid >> 5;
    if (n >= N_NODES) return;
    int lane = threadIdx.x & 31;
    int b = batch[n];
    float4 v = h2pre[n * 32 + lane];
    v.x = fmaxf(v.x, 0.f); v.y = fmaxf(v.y, 0.f);
    v.z = fmaxf(v.z, 0.f); v.w = fmaxf(v.w, 0.f);
    float* p = g_gsum + b * 128 + lane * 4;
    asm volatile("red.global.add.v4.f32 [%0], {%1,%2,%3,%4};"
                 :: "l"(p), "f"(v.x), "f"(v.y), "f"(v.z), "f"(v.w) : "memory");
    if (lane == 0) atomicAdd(&g_cnt[b], 1.f);
}

__global__ void div_kernel() {
    int idx = blockIdx.x * blockDim.x + threadIdx.x;
    if (idx >= N_GRAPHS * EMB) return;
    int g = idx >> 7;
    g_gsum[idx] = g_gsum[idx] / fmaxf(g_cnt[g], 1.f);
}

// ---------------- pair counting sort by cell line ----------------
__global__ void cl_count(const int* __restrict__ ecl) {
    int p = blockIdx.x * blockDim.x + threadIdx.x;
    if (p < N_PAIRS) atomicAdd(&g_clcnt[ecl[p]], 1);
}

__global__ void cl_scan() {
    if (threadIdx.x == 0) {
        int s = 0;
        for (int c = 0; c < N_CL; c++) {
            g_offs[c] = s;
            g_cursor[c] = s;
            s += g_clcnt[c];
        }
        g_offs[N_CL] = s;
    }
}

__global__ void cl_scatter(const int* __restrict__ ecl) {
    int p = blockIdx.x * blockDim.x + threadIdx.x;
    if (p >= N_PAIRS) return;
    int c = ecl[p];
    int pos = atomicAdd(&g_cursor[c], 1);
    g_sorted[pos] = p;
}

// ---------------- per-cell-line regressor GEMM ----------------
// block = (cl c, tile of 32 pairs); 256 threads; thread t owns hidden column t
__global__ void regressor(const float* __restrict__ W1, const float* __restrict__ B1,
                          const float* __restrict__ W2, const float* __restrict__ B2,
                          const int* __restrict__ ddb, float* __restrict__ out) {
    int c = blockIdx.x;
    int tile = blockIdx.y;
    int cnt = g_clcnt[c];
    if (tile * 32 >= cnt) return;

    __shared__ float As[32 * 256];
    __shared__ int   sp[32], g0s[32], g1s[32];
    __shared__ float red[32][9];

    int tid = threadIdx.x;
    int base = g_offs[c] + tile * 32;
    if (tid < 32) {
        int valid = (tile * 32 + tid) < cnt;
        int p = valid ? g_sorted[base + tid] : -1;
        sp[tid] = p;
        g0s[tid] = valid ? ddb[p] : 0;
        g1s[tid] = valid ? ddb[N_PAIRS + p] : 0;
    }
    __syncthreads();

#pragma unroll
    for (int i = tid; i < 32 * 256; i += 256) {
        int pi = i >> 8, e = i & 255;
        float v = (e < 128) ? g_gsum[g0s[pi] * 128 + e]
                            : g_gsum[g1s[pi] * 128 + (e - 128)];
        As[i] = v;
    }
    __syncthreads();

    const float* w1 = W1 + c * (2 * EMB * HID) + tid;
    float acc[32];
#pragma unroll
    for (int i = 0; i < 32; i++) acc[i] = 0.f;

    for (int k = 0; k < 256; k += 4) {
        float w0 = w1[(k + 0) * 256];
        float wA = w1[(k + 1) * 256];
        float wB = w1[(k + 2) * 256];
        float wC = w1[(k + 3) * 256];
#pragma unroll
        for (int i = 0; i < 32; i++) {
            float4 a = *(const float4*)&As[i * 256 + k];
            float t = acc[i];
            t = fmaf(a.x, w0, t);
            t = fmaf(a.y, wA, t);
            t = fmaf(a.z, wB, t);
            t = fmaf(a.w, wC, t);
            acc[i] = t;
        }
    }

    float b1t = B1[c * 256 + tid];
    float w2t = W2[c * 256 + tid];
    int warp = tid >> 5, lane = tid & 31;
#pragma unroll
    for (int i = 0; i < 32; i++) {
        float h = fmaxf(acc[i] + b1t, 0.f);
        float v = h * w2t;
#pragma unroll
        for (int off = 16; off; off >>= 1)
            v += __shfl_down_sync(0xffffffffu, v, off);
        if (lane == 0) red[i][warp] = v;
    }
    __syncthreads();
    if (tid < 32) {
        int p = sp[tid];
        if (p >= 0) {
            float s = B2[c];
#pragma unroll
            for (int w = 0; w < 8; w++) s += red[tid][w];
            out[p] = s;
        }
    }
}

// ---------------- launch ----------------
extern "C" void kernel_launch(void* const* d_in, const int* in_sizes, int n_in,
                              void* d_out, int out_size) {
    const float* x        = (const float*)d_in[0];
    const float* conv1_w  = (const float*)d_in[1];
    const float* conv1_b  = (const float*)d_in[2];
    const float* conv2_w  = (const float*)d_in[3];
    const float* conv2_b  = (const float*)d_in[4];
    const float* reg_w1   = (const float*)d_in[5];
    const float* reg_b1   = (const float*)d_in[6];
    const float* reg_w2   = (const float*)d_in[7];
    const float* reg_b2   = (const float*)d_in[8];
    const int*   ei       = (const int*)d_in[9];
    const int*   batch    = (const int*)d_in[10];
    const int*   ddb      = (const int*)d_in[11];
    const int*   ecl      = (const int*)d_in[12];
    float* out = (float*)d_out;

    float* bufHW;  cudaGetSymbolAddress((void**)&bufHW, g_bufHW);
    float* bufAGG; cudaGetSymbolAddress((void**)&bufAGG, g_bufAGG);

    init_kernel<<<(N_GRAPHS * EMB + 255) / 256, 256>>>();
    degree_kernel<<<(N_EDGES + 255) / 256, 256>>>(ei);
    dinv_kernel<<<(N_NODES + 255) / 256, 256>>>();

    // layer 1
    gemm_node<<<(N_NODES + 63) / 64, 256>>>(x, conv1_w, bufHW, N_NODES, IN_CH, 0);
    agg_init<<<(N_NODES * 32 + 255) / 256, 256>>>((const float4*)bufHW,
                                                  (const float4*)conv1_b, (float4*)bufAGG);
    agg_edges<<<(N_EDGES * 32 + 255) / 256, 256>>>((const float4*)bufHW, ei, bufAGG);

    // layer 2 (relu applied on GEMM input load)
    gemm_node<<<(N_NODES + 63) / 64, 256>>>(bufAGG, conv2_w, bufHW, N_NODES, EMB, 1);
    agg_init<<<(N_NODES * 32 + 255) / 256, 256>>>((const float4*)bufHW,
                                                  (const float4*)conv2_b, (float4*)bufAGG);
    agg_edges<<<(N_EDGES * 32 + 255) / 256, 256>>>((const float4*)bufHW, ei, bufAGG);

    // pooling (relu applied here)
    pool_kernel<<<(N_NODES * 32 + 255) / 256, 256>>>((const float4*)bufAGG, batch);
    div_kernel<<<(N_GRAPHS * EMB + 255) / 256, 256>>>();

    // counting sort pairs by cell line
    cl_count<<<(N_PAIRS + 255) / 256, 256>>>(ecl);
    cl_scan<<<1, 32>>>();
    cl_scatter<<<(N_PAIRS + 255) / 256, 256>>>(ecl);

    // per-cell-line MLP head (only the selected cell line per pair)
    dim3 rg(N_CL, (N_PAIRS + 31) / 32);
    regressor<<<rg, 256>>>(reg_w1, reg_b1, reg_w2, reg_b2, ddb, out);
}

// round 3
// speedup vs baseline: 1.2975x; 1.2975x over previous
#include <cuda_runtime.h>
#include <cuda_bf16.h>

#define N_NODES  50000
#define N_EDGES  800000
#define N_GRAPHS 1024
#define N_PAIRS  16384
#define N_CL     16
#define IN_CH    64
#define EMB      128
#define HID      256

#define SCAN_BLOCKS ((N_NODES + 255) / 256)   // 196

// ---------------- scratch (device globals; no allocations) ----------------
__device__ float g_bufHW[N_NODES * EMB];     // h1 / h2
__device__ float g_bufAGG[N_NODES * EMB];    // aggregated features
__device__ int   g_indeg[N_NODES];
__device__ float g_dinv[N_NODES];
__device__ int   g_rowptr[N_NODES + 1];
__device__ int   g_cursor2[N_NODES];
__device__ int   g_bsum[256];
__device__ int   g_boff[256];
__device__ int   g_csr_src[N_EDGES];
__device__ float g_csr_nrm[N_EDGES];
__device__ float g_gsum[N_GRAPHS * EMB];
__device__ float g_cnt[N_GRAPHS];
__device__ int   g_clcnt[N_CL];
__device__ int   g_offs[N_CL + 1];
__device__ int   g_cursor[N_CL];
__device__ int   g_sorted[N_PAIRS];

// ---------------- init ----------------
__global__ void init_kernel() {
    int i = blockIdx.x * blockDim.x + threadIdx.x;
    if (i < N_GRAPHS * EMB) g_gsum[i] = 0.f;
    if (i < N_NODES)  g_indeg[i] = 0;
    if (i < N_GRAPHS) g_cnt[i] = 0.f;
    if (i < N_CL)     g_clcnt[i] = 0;
}

// ---------------- degree ----------------
__global__ void degree_kernel(const int* __restrict__ ei) {
    int e = blockIdx.x * blockDim.x + threadIdx.x;
    if (e < N_EDGES) atomicAdd(&g_indeg[ei[N_EDGES + e]], 1);  // target = col
}

// ---------------- CSR build: 3-step exclusive scan over in-degrees ----------------
__global__ void scanA() {
    __shared__ int s[256];
    int t = threadIdx.x;
    int i = blockIdx.x * 256 + t;
    int v = (i < N_NODES) ? g_indeg[i] : 0;
    s[t] = v; __syncthreads();
#pragma unroll
    for (int off = 1; off < 256; off <<= 1) {
        int x = (t >= off) ? s[t - off] : 0;
        __syncthreads();
        s[t] += x;
        __syncthreads();
    }
    if (i < N_NODES) {
        g_rowptr[i] = s[t] - v;                       // block-local exclusive
        g_dinv[i] = rsqrtf((float)(v + 1));           // +1 self-loop
    }
    if (t == 255) g_bsum[blockIdx.x] = s[255];
}

__global__ void scanB() {
    __shared__ int s[256];
    int t = threadIdx.x;
    int v = (t < SCAN_BLOCKS) ? g_bsum[t] : 0;
    s[t] = v; __syncthreads();
#pragma unroll
    for (int off = 1; off < 256; off <<= 1) {
        int x = (t >= off) ? s[t - off] : 0;
        __syncthreads();
        s[t] += x;
        __syncthreads();
    }
    g_boff[t] = s[t] - v;
    if (t == 0) g_rowptr[N_NODES] = N_EDGES;
}

__global__ void scanC() {
    int i = blockIdx.x * 256 + threadIdx.x;
    if (i < N_NODES) {
        int r = g_rowptr[i] + g_boff[blockIdx.x];
        g_rowptr[i] = r;
        g_cursor2[i] = r;
    }
}

__global__ void csr_scatter(const int* __restrict__ ei) {
    int e = blockIdx.x * blockDim.x + threadIdx.x;
    if (e >= N_EDGES) return;
    int r = ei[e];
    int c = ei[N_EDGES + e];
    int pos = atomicAdd(&g_cursor2[c], 1);
    g_csr_src[pos] = r;
    g_csr_nrm[pos] = g_dinv[r] * g_dinv[c];
}

// ---------------- CSR gather aggregation: Y[n] = dinv[n]^2 * X[n] + sum nrm*X[src] --------
// warp per node, C channels, V = C/32 floats per lane
template <int C>
__global__ void agg_gather(const float* __restrict__ X, float* __restrict__ Y) {
    int w = (blockIdx.x * blockDim.x + threadIdx.x) >> 5;
    if (w >= N_NODES) return;
    int lane = threadIdx.x & 31;
    constexpr int V = C / 32;

    float d = g_dinv[w];
    float sn = d * d;
    float acc[V];
    const float* xp = X + (long)w * C + lane * V;
#pragma unroll
    for (int v = 0; v < V; v++) acc[v] = sn * __ldg(xp + v);

    int s = g_rowptr[w], e = g_rowptr[w + 1];
    int j = s;
    for (; j + 2 <= e; j += 2) {
        int s0 = __ldg(&g_csr_src[j]);
        int s1 = __ldg(&g_csr_src[j + 1]);
        float n0 = __ldg(&g_csr_nrm[j]);
        float n1 = __ldg(&g_csr_nrm[j + 1]);
        const float* p0 = X + (long)s0 * C + lane * V;
        const float* p1 = X + (long)s1 * C + lane * V;
        if constexpr (V == 4) {
            float4 a = *(const float4*)p0;
            float4 b = *(const float4*)p1;
            acc[0] = fmaf(n0, a.x, acc[0]); acc[1] = fmaf(n0, a.y, acc[1]);
            acc[2] = fmaf(n0, a.z, acc[2]); acc[3] = fmaf(n0, a.w, acc[3]);
            acc[0] = fmaf(n1, b.x, acc[0]); acc[1] = fmaf(n1, b.y, acc[1]);
            acc[2] = fmaf(n1, b.z, acc[2]); acc[3] = fmaf(n1, b.w, acc[3]);
        } else {
            float2 a = *(const float2*)p0;
            float2 b = *(const float2*)p1;
            acc[0] = fmaf(n0, a.x, acc[0]); acc[1] = fmaf(n0, a.y, acc[1]);
            acc[0] = fmaf(n1, b.x, acc[0]); acc[1] = fmaf(n1, b.y, acc[1]);
        }
    }
    if (j < e) {
        int s0 = __ldg(&g_csr_src[j]);
        float n0 = __ldg(&g_csr_nrm[j]);
        const float* p0 = X + (long)s0 * C + lane * V;
        if constexpr (V == 4) {
            float4 a = *(const float4*)p0;
            acc[0] = fmaf(n0, a.x, acc[0]); acc[1] = fmaf(n0, a.y, acc[1]);
            acc[2] = fmaf(n0, a.z, acc[2]); acc[3] = fmaf(n0, a.w, acc[3]);
        } else {
            float2 a = *(const float2*)p0;
            acc[0] = fmaf(n0, a.x, acc[0]); acc[1] = fmaf(n0, a.y, acc[1]);
        }
    }

    float* yp = Y + (long)w * C + lane * V;
    if constexpr (V == 4) {
        *(float4*)yp = make_float4(acc[0], acc[1], acc[2], acc[3]);
    } else {
        *(float2*)yp = make_float2(acc[0], acc[1]);
    }
}

// ---------------- node GEMM with fused bias+relu: Y = relu(X@W + b) ----------------
// 64 nodes per block, 256 threads, thread owns 4 nodes x 8 cols.
__global__ void gemm_node(const float* __restrict__ X, const float* __restrict__ W,
                          const float* __restrict__ B, float* __restrict__ Y,
                          int n, int K) {
    __shared__ float Xs[64 * 64];
    __shared__ float Ws[64 * 128];
    int tid = threadIdx.x;
    int cg = tid & 15;       // col group: cols cg*8 .. cg*8+7
    int ng = tid >> 4;       // node group: nodes ng*4 .. ng*4+3
    int n0 = blockIdx.x * 64;

    float acc[4][8];
#pragma unroll
    for (int j = 0; j < 4; j++)
#pragma unroll
        for (int q = 0; q < 8; q++) acc[j][q] = 0.f;

    for (int kt = 0; kt < K; kt += 64) {
#pragma unroll
        for (int i = tid; i < 64 * 128; i += 256) Ws[i] = W[kt * 128 + i];
#pragma unroll
        for (int i = tid; i < 64 * 64; i += 256) {
            int nl = i >> 6, kk = i & 63;
            int node = n0 + nl;
            Xs[nl * 64 + kk] = (node < n) ? X[(long)node * K + kt + kk] : 0.f;
        }
        __syncthreads();
#pragma unroll 8
        for (int kk = 0; kk < 64; kk++) {
            float4 wa = *(const float4*)&Ws[kk * 128 + cg * 8];
            float4 wb = *(const float4*)&Ws[kk * 128 + cg * 8 + 4];
#pragma unroll
            for (int j = 0; j < 4; j++) {
                float xv = Xs[(ng * 4 + j) * 64 + kk];
                acc[j][0] = fmaf(xv, wa.x, acc[j][0]);
                acc[j][1] = fmaf(xv, wa.y, acc[j][1]);
                acc[j][2] = fmaf(xv, wa.z, acc[j][2]);
                acc[j][3] = fmaf(xv, wa.w, acc[j][3]);
                acc[j][4] = fmaf(xv, wb.x, acc[j][4]);
                acc[j][5] = fmaf(xv, wb.y, acc[j][5]);
                acc[j][6] = fmaf(xv, wb.z, acc[j][6]);
                acc[j][7] = fmaf(xv, wb.w, acc[j][7]);
            }
        }
        __syncthreads();
    }
    float4 ba = *(const float4*)&B[cg * 8];
    float4 bb = *(const float4*)&B[cg * 8 + 4];
#pragma unroll
    for (int j = 0; j < 4; j++) {
        int node = n0 + ng * 4 + j;
        if (node < n) {
            float4 a, b;
            a.x = fmaxf(acc[j][0] + ba.x, 0.f);
            a.y = fmaxf(acc[j][1] + ba.y, 0.f);
            a.z = fmaxf(acc[j][2] + ba.z, 0.f);
            a.w = fmaxf(acc[j][3] + ba.w, 0.f);
            b.x = fmaxf(acc[j][4] + bb.x, 0.f);
            b.y = fmaxf(acc[j][5] + bb.y, 0.f);
            b.z = fmaxf(acc[j][6] + bb.z, 0.f);
            b.w = fmaxf(acc[j][7] + bb.w, 0.f);
            *(float4*)&Y[(long)node * 128 + cg * 8]     = a;
            *(float4*)&Y[(long)node * 128 + cg * 8 + 4] = b;
        }
    }
}

// ---------------- pooling: gsum[batch[n]] += h2[n] (already relu'd); cnt += 1 ------------
__global__ void pool_kernel(const float4* __restrict__ h2, const int* __restrict__ batch) {
    unsigned gtid = blockIdx.x * blockDim.x + threadIdx.x;
    int n = gtid >> 5;
    if (n >= N_NODES) return;
    int lane = threadIdx.x & 31;
    int b = batch[n];
    float4 v = h2[n * 32 + lane];
    float* p = g_gsum + b * 128 + lane * 4;
    asm volatile("red.global.add.v4.f32 [%0], {%1,%2,%3,%4};"
                 :: "l"(p), "f"(v.x), "f"(v.y), "f"(v.z), "f"(v.w) : "memory");
    if (lane == 0) atomicAdd(&g_cnt[b], 1.f);
}

__global__ void div_kernel() {
    int idx = blockIdx.x * blockDim.x + threadIdx.x;
    if (idx >= N_GRAPHS * EMB) return;
    int g = idx >> 7;
    g_gsum[idx] = g_gsum[idx] / fmaxf(g_cnt[g], 1.f);
}

// ---------------- pair counting sort by cell line ----------------
__global__ void cl_count(const int* __restrict__ ecl) {
    int p = blockIdx.x * blockDim.x + threadIdx.x;
    if (p < N_PAIRS) atomicAdd(&g_clcnt[ecl[p]], 1);
}

__global__ void cl_scan() {
    if (threadIdx.x == 0) {
        int s = 0;
        for (int c = 0; c < N_CL; c++) {
            g_offs[c] = s;
            g_cursor[c] = s;
            s += g_clcnt[c];
        }
        g_offs[N_CL] = s;
    }
}

__global__ void cl_scatter(const int* __restrict__ ecl) {
    int p = blockIdx.x * blockDim.x + threadIdx.x;
    if (p >= N_PAIRS) return;
    int c = ecl[p];
    int pos = atomicAdd(&g_cursor[c], 1);
    g_sorted[pos] = p;
}

// ---------------- per-cell-line regressor ----------------
__global__ void regressor(const float* __restrict__ W1, const float* __restrict__ B1,
                          const float* __restrict__ W2, const float* __restrict__ B2,
                          const int* __restrict__ ddb, float* __restrict__ out) {
    int c = blockIdx.x;
    int tile = blockIdx.y;
    int cnt = g_clcnt[c];
    if (tile * 32 >= cnt) return;

    __shared__ float As[32 * 256];
    __shared__ int   sp[32], g0s[32], g1s[32];
    __shared__ float red[32][9];

    int tid = threadIdx.x;
    int base = g_offs[c] + tile * 32;
    if (tid < 32) {
        int valid = (tile * 32 + tid) < cnt;
        int p = valid ? g_sorted[base + tid] : -1;
        sp[tid] = p;
        g0s[tid] = valid ? ddb[p] : 0;
        g1s[tid] = valid ? ddb[N_PAIRS + p] : 0;
    }
    __syncthreads();

#pragma unroll
    for (int i = tid; i < 32 * 256; i += 256) {
        int pi = i >> 8, e = i & 255;
        As[i] = (e < 128) ? g_gsum[g0s[pi] * 128 + e]
                          : g_gsum[g1s[pi] * 128 + (e - 128)];
    }
    __syncthreads();

    const float* w1 = W1 + c * (2 * EMB * HID) + tid;
    float acc[32];
#pragma unroll
    for (int i = 0; i < 32; i++) acc[i] = 0.f;

    for (int k = 0; k < 256; k += 4) {
        float w0 = w1[(k + 0) * 256];
        float wA = w1[(k + 1) * 256];
        float wB = w1[(k + 2) * 256];
        float wC = w1[(k + 3) * 256];
#pragma unroll
        for (int i = 0; i < 32; i++) {
            float4 a = *(const float4*)&As[i * 256 + k];
            float t = acc[i];
            t = fmaf(a.x, w0, t);
            t = fmaf(a.y, wA, t);
            t = fmaf(a.z, wB, t);
            t = fmaf(a.w, wC, t);
            acc[i] = t;
        }
    }

    float b1t = B1[c * 256 + tid];
    float w2t = W2[c * 256 + tid];
    int warp = tid >> 5, lane = tid & 31;
#pragma unroll
    for (int i = 0; i < 32; i++) {
        float h = fmaxf(acc[i] + b1t, 0.f);
        float v = h * w2t;
#pragma unroll
        for (int off = 16; off; off >>= 1)
            v += __shfl_down_sync(0xffffffffu, v, off);
        if (lane == 0) red[i][warp] = v;
    }
    __syncthreads();
    if (tid < 32) {
        int p = sp[tid];
        if (p >= 0) {
            float s = B2[c];
#pragma unroll
            for (int w = 0; w < 8; w++) s += red[tid][w];
            out[p] = s;
        }
    }
}

// ---------------- launch ----------------
extern "C" void kernel_launch(void* const* d_in, const int* in_sizes, int n_in,
                              void* d_out, int out_size) {
    const float* x        = (const float*)d_in[0];
    const float* conv1_w  = (const float*)d_in[1];
    const float* conv1_b  = (const float*)d_in[2];
    const float* conv2_w  = (const float*)d_in[3];
    const float* conv2_b  = (const float*)d_in[4];
    const float* reg_w1   = (const float*)d_in[5];
    const float* reg_b1   = (const float*)d_in[6];
    const float* reg_w2   = (const float*)d_in[7];
    const float* reg_b2   = (const float*)d_in[8];
    const int*   ei       = (const int*)d_in[9];
    const int*   batch    = (const int*)d_in[10];
    const int*   ddb      = (const int*)d_in[11];
    const int*   ecl      = (const int*)d_in[12];
    float* out = (float*)d_out;

    float* bufHW;  cudaGetSymbolAddress((void**)&bufHW, g_bufHW);
    float* bufAGG; cudaGetSymbolAddress((void**)&bufAGG, g_bufAGG);

    init_kernel<<<(N_GRAPHS * EMB + 255) / 256, 256>>>();
    degree_kernel<<<(N_EDGES + 255) / 256, 256>>>(ei);
    scanA<<<SCAN_BLOCKS, 256>>>();
    scanB<<<1, 256>>>();
    scanC<<<SCAN_BLOCKS, 256>>>();
    csr_scatter<<<(N_EDGES + 255) / 256, 256>>>(ei);

    // pair sort (independent of GCN) — interleave early
    cl_count<<<(N_PAIRS + 255) / 256, 256>>>(ecl);
    cl_scan<<<1, 32>>>();
    cl_scatter<<<(N_PAIRS + 255) / 256, 256>>>(ecl);

    // layer 1: aggregate x (64 ch) then transform (A x) @ W1 + b1, relu
    agg_gather<IN_CH><<<(N_NODES * 32 + 255) / 256, 256>>>(x, bufAGG);
    gemm_node<<<(N_NODES + 63) / 64, 256>>>(bufAGG, conv1_w, conv1_b, bufHW, N_NODES, IN_CH);

    // layer 2: aggregate h1 (128 ch) then transform
    agg_gather<EMB><<<(N_NODES * 32 + 255) / 256, 256>>>(bufHW, bufAGG);
    gemm_node<<<(N_NODES + 63) / 64, 256>>>(bufAGG, conv2_w, conv2_b, bufHW, N_NODES, EMB);

    // pooling
    pool_kernel<<<(N_NODES * 32 + 255) / 256, 256>>>((const float4*)bufHW, batch);
    div_kernel<<<(N_GRAPHS * EMB + 255) / 256, 256>>>();

    // per-cell-line MLP head
    dim3 rg(N_CL, (N_PAIRS + 31) / 32);
    regressor<<<rg, 256>>>(reg_w1, reg_b1, reg_w2, reg_b2, ddb, out);
}